// round 13
// baseline (speedup 1.0000x reference)
#include <cuda_runtime.h>
#include <cstdint>

#define TT 8192
#define HH 16
#define DD 128
#define HD (HH * DD)        // 2048
#define C3 (3 * HD)         // 6144
#define NCB 8               // column blocks per head
#define CPB 16              // columns per block
#define GS 8                // steps per smem stage = group size
#define NG (TT / GS)        // 1024 groups per head
#define NBUF 3              // operand stages

typedef unsigned long long u64;

// ---------------- scratch (static device memory; no allocs allowed) --------
__device__ float g_q  [HH * TT * DD];   // [H][T][D]
__device__ float g_k  [HH * TT * DD];   // [H][T][D]
__device__ float g_dec[HH * TT * DD];   // [H][T][D]
__device__ float g_v  [HH * TT * DD];   // [H][T][D]
__device__ float g_KG [HH * TT * DD];   // [H][T][D] G_i∘k_i
__device__ float g_QG [HH * TT * DD];   // [H][T][D] G_i∘q_i
__device__ float g_KP [HH * TT * DD];   // [H][T][D] suffix-decayed keys
__device__ float g_G7 [HH * NG * DD];   // [H][NG][D] full-group decay
__device__ float g_b  [HH * TT];        // [H][T]
__device__ float g_c  [HH * NG * 128];  // [H][NG][128]: [0..64) solve C, [64..128) CQ

// ---------------- packed f32x2 helpers (sm_103a) ---------------------------
__device__ __forceinline__ u64 fma2(u64 a, u64 b, u64 c) {
    u64 d; asm("fma.rn.f32x2 %0, %1, %2, %3;" : "=l"(d) : "l"(a), "l"(b), "l"(c)); return d;
}
__device__ __forceinline__ u64 mul2(u64 a, u64 b) {
    u64 d; asm("mul.rn.f32x2 %0, %1, %2;" : "=l"(d) : "l"(a), "l"(b)); return d;
}
__device__ __forceinline__ float hsum2(u64 a) {
    float x, y; asm("mov.b64 {%0, %1}, %2;" : "=f"(x), "=f"(y) : "l"(a)); return x + y;
}
__device__ __forceinline__ u64 pack2(float x) {
    u64 d; asm("mov.b64 %0, {%1, %1};" : "=l"(d) : "f"(x)); return d;
}
__device__ __forceinline__ void cpa16(void* dst, const void* src) {
    unsigned d = (unsigned)__cvta_generic_to_shared(dst);
    asm volatile("cp.async.ca.shared.global [%0], [%1], 16;" :: "r"(d), "l"(src));
}
__device__ __forceinline__ float softplusf(float x) {
    return (x > 20.f) ? x : log1pf(expf(x));
}
__device__ __forceinline__ float dot4(float4 a, float4 b) {
    return a.x * b.x + a.y * b.y + a.z * b.z + a.w * b.w;
}

// ---------------- dummy kernel: keeps ncu's profiled slot on the scan ------
__global__ void dummy_kernel() {}

// ============================================================================
// Phase 1: conv1d + SiLU, l2norm(q,k), gates  -> transposed [H][T][D] scratch
// ============================================================================
__global__ void prep_kernel(const float* __restrict__ xin,   // [T, 3HD]
                            const float* __restrict__ fg,    // [T, HD]
                            const float* __restrict__ beta,  // [T, H]
                            const float* __restrict__ cw,    // [3HD, 4]
                            const float* __restrict__ dtb,   // [H, D]
                            const float* __restrict__ alog)  // [H]
{
    const int t   = blockIdx.x;
    const int tid = threadIdx.x;                 // 256 threads

    __shared__ float sbuf[C3];
    __shared__ float snorm[32];
    __shared__ float snegA[HH];

    if (tid < HH) snegA[tid] = -expf(alog[tid]);

    const float4* x4  = (const float4*)xin;      // [T, 1536]
    const float4* w4  = (const float4*)cw;
    float4* sbuf4 = (float4*)sbuf;

    #pragma unroll
    for (int it = 0; it < 6; it++) {
        int c4 = tid + it * 256;                 // 0..1535
        float4 w0 = w4[c4 * 4 + 0];
        float4 w1 = w4[c4 * 4 + 1];
        float4 w2 = w4[c4 * 4 + 2];
        float4 w3 = w4[c4 * 4 + 3];
        float4 a0 = x4[(size_t)t * 1536 + c4];
        float4 acc;
        acc.x = a0.x * w0.w; acc.y = a0.y * w1.w;
        acc.z = a0.z * w2.w; acc.w = a0.w * w3.w;
        if (t >= 1) {
            float4 a = x4[(size_t)(t - 1) * 1536 + c4];
            acc.x += a.x * w0.z; acc.y += a.y * w1.z;
            acc.z += a.z * w2.z; acc.w += a.w * w3.z;
        }
        if (t >= 2) {
            float4 a = x4[(size_t)(t - 2) * 1536 + c4];
            acc.x += a.x * w0.y; acc.y += a.y * w1.y;
            acc.z += a.z * w2.y; acc.w += a.w * w3.y;
        }
        if (t >= 3) {
            float4 a = x4[(size_t)(t - 3) * 1536 + c4];
            acc.x += a.x * w0.x; acc.y += a.y * w1.x;
            acc.z += a.z * w2.x; acc.w += a.w * w3.x;
        }
        acc.x = acc.x / (1.f + expf(-acc.x));
        acc.y = acc.y / (1.f + expf(-acc.y));
        acc.z = acc.z / (1.f + expf(-acc.z));
        acc.w = acc.w / (1.f + expf(-acc.w));
        sbuf4[c4] = acc;
    }
    __syncthreads();

    const int wid = tid >> 5, lane = tid & 31;
    for (int g = wid; g < 32; g += 8) {
        const int base = g * 128;
        float v0 = sbuf[base + lane];
        float v1 = sbuf[base + 32 + lane];
        float v2 = sbuf[base + 64 + lane];
        float v3 = sbuf[base + 96 + lane];
        float ss = v0 * v0 + v1 * v1 + v2 * v2 + v3 * v3;
        #pragma unroll
        for (int off = 16; off > 0; off >>= 1)
            ss += __shfl_xor_sync(0xffffffffu, ss, off);
        if (lane == 0) snorm[g] = rsqrtf(ss + 1e-6f);
    }
    __syncthreads();

    const float qscale = 0.08838834764831845f;   // D^-0.5
    #pragma unroll
    for (int it = 0; it < 6; it++) {
        int c4 = tid + it * 256;
        int c  = c4 * 4;
        float4 val = sbuf4[c4];
        if (c < HD) {
            int h = c >> 7, d = c & 127;
            float sc = snorm[h] * qscale;
            val.x *= sc; val.y *= sc; val.z *= sc; val.w *= sc;
            ((float4*)g_q)[((size_t)h * TT + t) * 32 + (d >> 2)] = val;
        } else if (c < 2 * HD) {
            int cc = c - HD; int h = cc >> 7, d = cc & 127;
            float sc = snorm[16 + h];
            val.x *= sc; val.y *= sc; val.z *= sc; val.w *= sc;
            ((float4*)g_k)[((size_t)h * TT + t) * 32 + (d >> 2)] = val;
        } else {
            int cc = c - 2 * HD; int h = cc >> 7, d = cc & 127;
            ((float4*)g_v)[((size_t)h * TT + t) * 32 + (d >> 2)] = val;
        }
    }

    const float4* fg4  = (const float4*)fg;
    const float4* dtb4 = (const float4*)dtb;
    #pragma unroll
    for (int it = 0; it < 2; it++) {
        int c4 = tid + it * 256;                 // 0..511
        int h  = (c4 * 4) >> 7;
        float na = snegA[h];
        float4 gg = fg4[(size_t)t * 512 + c4];
        float4 bb = dtb4[c4];
        float4 r;
        r.x = expf(na * softplusf(gg.x + bb.x));
        r.y = expf(na * softplusf(gg.y + bb.y));
        r.z = expf(na * softplusf(gg.z + bb.z));
        r.w = expf(na * softplusf(gg.w + bb.w));
        ((float4*)g_dec)[((size_t)h * TT + t) * 32 + (((c4 * 4) & 127) >> 2)] = r;
    }
    if (tid < HH)
        g_b[tid * TT + t] = 1.f / (1.f + expf(-beta[(size_t)t * HH + tid]));
}

// ============================================================================
// Phase 1b: group operators + solve/output matrices. One warp per group.
// ============================================================================
__global__ void __launch_bounds__(128)
group_prep_kernel()
{
    const int h    = blockIdx.y;
    const int g    = blockIdx.x * 4 + (threadIdx.x >> 5);
    const int lane = threadIdx.x & 31;

    const size_t base = ((size_t)h * TT + (size_t)g * GS) * DD;
    const float4* kp4 = (const float4*)(g_k   + base);
    const float4* dp4 = (const float4*)(g_dec + base);
    const float4* qp4 = (const float4*)(g_q   + base);
    float4* KGout = (float4*)(g_KG + base);
    float4* QGout = (float4*)(g_QG + base);
    float4* KPout = (float4*)(g_KP + base);
    float4* G7out = (float4*)(g_G7 + ((size_t)h * NG + g) * DD);

    float4 dv[GS], kv[GS], qv[GS];
    #pragma unroll
    for (int i = 0; i < GS; i++) {
        dv[i] = dp4[i * 32 + lane];
        kv[i] = kp4[i * 32 + lane];
        qv[i] = qp4[i * 32 + lane];
    }

    // prefix decay products -> KG, QG, G7
    {
        float4 G = make_float4(1.f, 1.f, 1.f, 1.f);
        #pragma unroll
        for (int i = 0; i < GS; i++) {
            G.x *= dv[i].x; G.y *= dv[i].y; G.z *= dv[i].z; G.w *= dv[i].w;
            float4 o;
            o.x = G.x * kv[i].x; o.y = G.y * kv[i].y;
            o.z = G.z * kv[i].z; o.w = G.w * kv[i].w;
            KGout[i * 32 + lane] = o;
            o.x = G.x * qv[i].x; o.y = G.y * qv[i].y;
            o.z = G.z * qv[i].z; o.w = G.w * qv[i].w;
            QGout[i * 32 + lane] = o;
        }
        G7out[lane] = G;
    }

    float r[64];
    #pragma unroll
    for (int i = 0; i < GS; i++) r[i * 9] = dot4(qv[i], kv[i]);

    #pragma unroll
    for (int j = 0; j < GS; j++) {
        float4 w = kv[j];
        #pragma unroll
        for (int i = j + 1; i < GS; i++) {
            w.x *= dv[i].x; w.y *= dv[i].y; w.z *= dv[i].z; w.w *= dv[i].w;
            r[i * 8 + j] = dot4(kv[i], w);   // c_ij (lower)
            r[j * 8 + i] = dot4(qv[i], w);   // cq_ij (upper slot)
        }
        KPout[j * 32 + lane] = w;            // suffix-decayed key
    }

    #pragma unroll
    for (int off = 16; off > 0; off >>= 1) {
        #pragma unroll
        for (int m = 0; m < 64; m++)
            r[m] += __shfl_xor_sync(0xffffffffu, r[m], off);
    }
    if (lane == 0) {
        float* co = g_c + ((size_t)h * NG + g) * 128;
        #pragma unroll
        for (int m = 0; m < 64; m++) co[m] = r[m];
        #pragma unroll
        for (int i = 0; i < GS; i++)
            #pragma unroll
            for (int j = 0; j < GS; j++)
                co[64 + i * 8 + j] = (j < i) ? r[j * 8 + i]
                                  : (j == i) ? r[i * 9] : 0.f;
    }
}

// ============================================================================
// Phase 2: warp-specialized 8-step-group scan, 256 threads.
// Warps 0-3 (A): km dots -> reduce -> solve -> del.  Warps 4-7 (B): output
// dots + reduce + store.  Both maintain bitwise-identical S copies (4 cols
// per warp-slot, lane owns D[4L,4L+4)) and apply the same update from del.
// ============================================================================

#define RSTAGE_SPLIT(r, n, o) do {                                          \
    const bool _hi = (lane & (o)) != 0;                                     \
    _Pragma("unroll")                                                       \
    for (int _j = 0; _j < (n); _j++) {                                      \
        float _send = _hi ? r[_j] : r[_j + (n)];                            \
        float _recv = __shfl_xor_sync(0xffffffffu, _send, (o));             \
        r[_j] = (_hi ? r[_j + (n)] : r[_j]) + _recv;                        \
    }                                                                       \
} while (0)

#define PREFETCH(slot, t0) do {                                             \
    {                                                                       \
        size_t _go = (size_t)((t0) + (tid >> 5)) * DD + (tid & 31) * 4;     \
        cpa16(&sKG[slot][tid >> 5][tid & 31], KGg + _go);                   \
        cpa16(&sQG[slot][tid >> 5][tid & 31], QGg + _go);                   \
        cpa16(&sKP[slot][tid >> 5][tid & 31], KPg + _go);                   \
    }                                                                       \
    if (tid < 32) {                                                         \
        cpa16(&sG7[slot][tid], G7g + (size_t)((t0) >> 3) * DD + tid * 4);   \
    } else if (tid < 64) {                                                  \
        int _c = tid - 32;                                                  \
        cpa16(&sv[slot][_c >> 2][(_c & 3) * 4],                             \
              vg + (size_t)((t0) + (_c >> 2)) * DD + (_c & 3) * 4);         \
    } else if (tid < 96) {                                                  \
        int _m = tid - 64;                                                  \
        cpa16(&sc[slot][_m * 4],                                            \
              cg + (size_t)((t0) >> 3) * 128 + _m * 4);                     \
    } else if (tid < 98) {                                                  \
        int _j2 = tid - 96;                                                 \
        cpa16(&sb[slot][_j2 * 4], bg + (t0) + _j2 * 4);                     \
    }                                                                       \
} while (0)

__global__ void __launch_bounds__(256, 1)
kda_scan_kernel(float* __restrict__ out)
{
    __shared__ __align__(16) ulonglong2 sKG[NBUF][GS][32];
    __shared__ __align__(16) ulonglong2 sQG[NBUF][GS][32];
    __shared__ __align__(16) ulonglong2 sKP[NBUF][GS][32];
    __shared__ __align__(16) ulonglong2 sG7[NBUF][32];
    __shared__ __align__(16) float      sv[NBUF][GS][16];
    __shared__ __align__(16) float      sb[NBUF][GS];
    __shared__ __align__(16) float      sc[NBUF][128];
    __shared__ __align__(16) float      sdel[2][GS][20];   // stride-20: bank-clean

    const int h    = blockIdx.y;
    const int cb   = blockIdx.x;
    const int tid  = threadIdx.x;
    const int lane = tid & 31;
    const int wid  = tid >> 5;
    const bool isA = (wid < 4);
    const int wq   = wid & 3;            // column block within side: cols [4wq,4wq+4)
    const int cgrp = (lane >> 3) & 3;    // lane's solve/output column
    const int myi  = lane & 7;           // lane's output step
    const int colloc = 4 * wq + cgrp;

    const size_t hbase = (size_t)h * TT * DD;
    const float* KGg = g_KG + hbase;
    const float* QGg = g_QG + hbase;
    const float* KPg = g_KP + hbase;
    const float* G7g = g_G7 + (size_t)h * NG * DD;
    const float* vg  = g_v  + hbase + cb * CPB;
    const float* bg  = g_b  + (size_t)h * TT;
    const float* cg  = g_c  + (size_t)h * NG * 128;
    float* op = out + (size_t)h * DD + cb * CPB + colloc;

    // state copy (A and B bitwise identical): st[c][p], c = local col, p = pair
    u64 st[4][2];
    #pragma unroll
    for (int c = 0; c < 4; c++) { st[c][0] = 0ull; st[c][1] = 0ull; }

    PREFETCH(0, 0);
    asm volatile("cp.async.commit_group;" ::: "memory");
    PREFETCH(1, GS);
    asm volatile("cp.async.commit_group;" ::: "memory");

    int db = 0;
    #pragma unroll 1
    for (int t0 = 0; t0 < TT; t0 += GS) {
        const int slot = (t0 >> 3) % NBUF;
        asm volatile("cp.async.wait_group 1;" ::: "memory");
        __syncthreads();                               // bar#1: operands ready

        // prefetch 2 groups ahead into the slot freed by the previous group
        if (t0 + 2 * GS < TT) {
            PREFETCH((slot + 2) % NBUF, t0 + 2 * GS);
        }
        asm volatile("cp.async.commit_group;" ::: "memory");

        float xout = 0.f;                              // B: o-partial (myi,cgrp)
        if (isA) {
            // ---- km dots ----
            float r[32];
            #pragma unroll
            for (int i = 0; i < GS; i++) {
                ulonglong2 kg = sKG[slot][i][lane];
                #pragma unroll
                for (int c = 0; c < 4; c++) {
                    u64 t = mul2(kg.x, st[c][0]);
                    t = fma2(kg.y, st[c][1], t);
                    r[8 * c + i] = hsum2(t);
                }
            }
            // ---- reduce: 2 split stages, then 8-lane all-reduce ----
            RSTAGE_SPLIT(r, 16, 16);
            RSTAGE_SPLIT(r,  8,  8);
            #pragma unroll
            for (int o = 4; o >= 1; o >>= 1) {
                #pragma unroll
                for (int j = 0; j < 8; j++)
                    r[j] += __shfl_xor_sync(0xffffffffu, r[j], o);
            }
            // ---- triangular solve for column cgrp ----
            float del[8];
            del[0] = sb[slot][0] * (sv[slot][0][colloc] - r[0]);
            #pragma unroll
            for (int i = 1; i < GS; i++) {
                float acc = r[i];
                #pragma unroll
                for (int j = 0; j < i; j++)
                    acc = fmaf(sc[slot][i * 8 + j], del[j], acc);
                del[i] = sb[slot][i] * (sv[slot][i][colloc] - acc);
            }
            // ---- publish del (lane myi writes row myi of its column) ----
            #pragma unroll
            for (int i = 0; i < GS; i++)
                if (myi == i) sdel[db][i][colloc] = del[i];
        } else {
            // ---- output dots (pre-update S) ----
            float x[32];
            #pragma unroll
            for (int i = 0; i < GS; i++) {
                ulonglong2 qg = sQG[slot][i][lane];
                #pragma unroll
                for (int c = 0; c < 4; c++) {
                    u64 t = mul2(qg.x, st[c][0]);
                    t = fma2(qg.y, st[c][1], t);
                    x[8 * c + i] = hsum2(t);
                }
            }
            // ---- full split-reduce -> x[0] = o_partial(myi, cgrp) ----
            RSTAGE_SPLIT(x, 16, 16);
            RSTAGE_SPLIT(x,  8,  8);
            RSTAGE_SPLIT(x,  4,  4);
            RSTAGE_SPLIT(x,  2,  2);
            RSTAGE_SPLIT(x,  1,  1);
            xout = x[0];
        }

        __syncthreads();                               // bar#2: del ready

        // ---- shared: state update st = G7∘st + sum_i KP_i * del_i ----
        {
            ulonglong2 g7 = sG7[slot][lane];
            #pragma unroll
            for (int c = 0; c < 4; c++) {
                st[c][0] = mul2(g7.x, st[c][0]);
                st[c][1] = mul2(g7.y, st[c][1]);
            }
        }
        #pragma unroll
        for (int i = 0; i < GS; i++) {
            float4 dr = *(const float4*)&sdel[db][i][4 * wq];
            ulonglong2 kp = sKP[slot][i][lane];
            u64 d0 = pack2(dr.x), d1 = pack2(dr.y);
            u64 d2 = pack2(dr.z), d3 = pack2(dr.w);
            st[0][0] = fma2(kp.x, d0, st[0][0]); st[0][1] = fma2(kp.y, d0, st[0][1]);
            st[1][0] = fma2(kp.x, d1, st[1][0]); st[1][1] = fma2(kp.y, d1, st[1][1]);
            st[2][0] = fma2(kp.x, d2, st[2][0]); st[2][1] = fma2(kp.y, d2, st[2][1]);
            st[3][0] = fma2(kp.x, d3, st[3][0]); st[3][1] = fma2(kp.y, d3, st[3][1]);
        }

        // ---- B: finish outputs ----
        if (!isA) {
            const float* cqp = &sc[slot][64 + myi * 8];
            float oo = xout;
            #pragma unroll
            for (int j = 0; j < GS; j++)
                oo = fmaf(cqp[j], sdel[db][j][colloc], oo);
            op[(size_t)(t0 + myi) * HD] = oo;
        }

        db ^= 1;
    }
}

// ============================================================================
extern "C" void kernel_launch(void* const* d_in, const int* in_sizes, int n_in,
                              void* d_out, int out_size)
{
    const float* mixed = (const float*)d_in[0];   // [T, 3HD]
    const float* fg    = (const float*)d_in[1];   // [T, HD]
    const float* beta  = (const float*)d_in[2];   // [T, H]
    const float* cw    = (const float*)d_in[3];   // [3HD, 4]
    const float* dtb   = (const float*)d_in[4];   // [H, D]
    const float* alog  = (const float*)d_in[5];   // [H]
    float* out = (float*)d_out;                   // [T, H, D] f32

    dummy_kernel<<<1, 32>>>();                    // keeps ncu slot on the scan
    prep_kernel<<<TT, 256>>>(mixed, fg, beta, cw, dtb, alog);
    group_prep_kernel<<<dim3(NG / 4, HH), 128>>>();
    kda_scan_kernel<<<dim3(NCB, HH), 256>>>(out);
}

// round 14
// speedup vs baseline: 1.0154x; 1.0154x over previous
#include <cuda_runtime.h>
#include <cstdint>

#define TT 8192
#define HH 16
#define DD 128
#define HD (HH * DD)        // 2048
#define C3 (3 * HD)         // 6144
#define NCB 8               // column blocks per head
#define CPB 16              // columns per block
#define GS 8                // steps per smem stage = group size
#define NG (TT / GS)        // 1024 groups per head
#define NBUF 3              // operand stages

typedef unsigned long long u64;

// ---------------- scratch (static device memory; no allocs allowed) --------
__device__ float g_q  [HH * TT * DD];   // [H][T][D]
__device__ float g_k  [HH * TT * DD];   // [H][T][D]
__device__ float g_dec[HH * TT * DD];   // [H][T][D]
__device__ float g_v  [HH * TT * DD];   // [H][T][D]
__device__ float g_KG [HH * TT * DD];   // [H][T][D] G_i∘k_i
__device__ float g_QG [HH * TT * DD];   // [H][T][D] G_i∘q_i
__device__ float g_KP [HH * TT * DD];   // [H][T][D] suffix-decayed keys
__device__ float g_G7 [HH * NG * DD];   // [H][NG][D] full-group decay
__device__ float g_b  [HH * TT];        // [H][T]
__device__ float g_c  [HH * NG * 128];  // [H][NG][128]: [0..64) solve C, [64..128) CQ

// ---------------- packed f32x2 helpers (sm_103a) ---------------------------
__device__ __forceinline__ u64 fma2(u64 a, u64 b, u64 c) {
    u64 d; asm("fma.rn.f32x2 %0, %1, %2, %3;" : "=l"(d) : "l"(a), "l"(b), "l"(c)); return d;
}
__device__ __forceinline__ u64 mul2(u64 a, u64 b) {
    u64 d; asm("mul.rn.f32x2 %0, %1, %2;" : "=l"(d) : "l"(a), "l"(b)); return d;
}
__device__ __forceinline__ float hsum2(u64 a) {
    float x, y; asm("mov.b64 {%0, %1}, %2;" : "=f"(x), "=f"(y) : "l"(a)); return x + y;
}
__device__ __forceinline__ u64 pack2(float x) {
    u64 d; asm("mov.b64 %0, {%1, %1};" : "=l"(d) : "f"(x)); return d;
}
__device__ __forceinline__ void cpa16(void* dst, const void* src) {
    unsigned d = (unsigned)__cvta_generic_to_shared(dst);
    asm volatile("cp.async.ca.shared.global [%0], [%1], 16;" :: "r"(d), "l"(src));
}
__device__ __forceinline__ float softplusf(float x) {
    return (x > 20.f) ? x : log1pf(expf(x));
}
__device__ __forceinline__ float dot4(float4 a, float4 b) {
    return a.x * b.x + a.y * b.y + a.z * b.z + a.w * b.w;
}

// ---------------- dummy kernel: keeps ncu's profiled slot on the scan ------
__global__ void dummy_kernel() {}

// ============================================================================
// Phase 1: conv1d + SiLU, l2norm(q,k), gates  -> transposed [H][T][D] scratch
// ============================================================================
__global__ void prep_kernel(const float* __restrict__ xin,   // [T, 3HD]
                            const float* __restrict__ fg,    // [T, HD]
                            const float* __restrict__ beta,  // [T, H]
                            const float* __restrict__ cw,    // [3HD, 4]
                            const float* __restrict__ dtb,   // [H, D]
                            const float* __restrict__ alog)  // [H]
{
    const int t   = blockIdx.x;
    const int tid = threadIdx.x;                 // 256 threads

    __shared__ float sbuf[C3];
    __shared__ float snorm[32];
    __shared__ float snegA[HH];

    if (tid < HH) snegA[tid] = -expf(alog[tid]);

    const float4* x4  = (const float4*)xin;      // [T, 1536]
    const float4* w4  = (const float4*)cw;
    float4* sbuf4 = (float4*)sbuf;

    #pragma unroll
    for (int it = 0; it < 6; it++) {
        int c4 = tid + it * 256;                 // 0..1535
        float4 w0 = w4[c4 * 4 + 0];
        float4 w1 = w4[c4 * 4 + 1];
        float4 w2 = w4[c4 * 4 + 2];
        float4 w3 = w4[c4 * 4 + 3];
        float4 a0 = x4[(size_t)t * 1536 + c4];
        float4 acc;
        acc.x = a0.x * w0.w; acc.y = a0.y * w1.w;
        acc.z = a0.z * w2.w; acc.w = a0.w * w3.w;
        if (t >= 1) {
            float4 a = x4[(size_t)(t - 1) * 1536 + c4];
            acc.x += a.x * w0.z; acc.y += a.y * w1.z;
            acc.z += a.z * w2.z; acc.w += a.w * w3.z;
        }
        if (t >= 2) {
            float4 a = x4[(size_t)(t - 2) * 1536 + c4];
            acc.x += a.x * w0.y; acc.y += a.y * w1.y;
            acc.z += a.z * w2.y; acc.w += a.w * w3.y;
        }
        if (t >= 3) {
            float4 a = x4[(size_t)(t - 3) * 1536 + c4];
            acc.x += a.x * w0.x; acc.y += a.y * w1.x;
            acc.z += a.z * w2.x; acc.w += a.w * w3.x;
        }
        acc.x = acc.x / (1.f + expf(-acc.x));
        acc.y = acc.y / (1.f + expf(-acc.y));
        acc.z = acc.z / (1.f + expf(-acc.z));
        acc.w = acc.w / (1.f + expf(-acc.w));
        sbuf4[c4] = acc;
    }
    __syncthreads();

    const int wid = tid >> 5, lane = tid & 31;
    for (int g = wid; g < 32; g += 8) {
        const int base = g * 128;
        float v0 = sbuf[base + lane];
        float v1 = sbuf[base + 32 + lane];
        float v2 = sbuf[base + 64 + lane];
        float v3 = sbuf[base + 96 + lane];
        float ss = v0 * v0 + v1 * v1 + v2 * v2 + v3 * v3;
        #pragma unroll
        for (int off = 16; off > 0; off >>= 1)
            ss += __shfl_xor_sync(0xffffffffu, ss, off);
        if (lane == 0) snorm[g] = rsqrtf(ss + 1e-6f);
    }
    __syncthreads();

    const float qscale = 0.08838834764831845f;   // D^-0.5
    #pragma unroll
    for (int it = 0; it < 6; it++) {
        int c4 = tid + it * 256;
        int c  = c4 * 4;
        float4 val = sbuf4[c4];
        if (c < HD) {
            int h = c >> 7, d = c & 127;
            float sc = snorm[h] * qscale;
            val.x *= sc; val.y *= sc; val.z *= sc; val.w *= sc;
            ((float4*)g_q)[((size_t)h * TT + t) * 32 + (d >> 2)] = val;
        } else if (c < 2 * HD) {
            int cc = c - HD; int h = cc >> 7, d = cc & 127;
            float sc = snorm[16 + h];
            val.x *= sc; val.y *= sc; val.z *= sc; val.w *= sc;
            ((float4*)g_k)[((size_t)h * TT + t) * 32 + (d >> 2)] = val;
        } else {
            int cc = c - 2 * HD; int h = cc >> 7, d = cc & 127;
            ((float4*)g_v)[((size_t)h * TT + t) * 32 + (d >> 2)] = val;
        }
    }

    const float4* fg4  = (const float4*)fg;
    const float4* dtb4 = (const float4*)dtb;
    #pragma unroll
    for (int it = 0; it < 2; it++) {
        int c4 = tid + it * 256;                 // 0..511
        int h  = (c4 * 4) >> 7;
        float na = snegA[h];
        float4 gg = fg4[(size_t)t * 512 + c4];
        float4 bb = dtb4[c4];
        float4 r;
        r.x = expf(na * softplusf(gg.x + bb.x));
        r.y = expf(na * softplusf(gg.y + bb.y));
        r.z = expf(na * softplusf(gg.z + bb.z));
        r.w = expf(na * softplusf(gg.w + bb.w));
        ((float4*)g_dec)[((size_t)h * TT + t) * 32 + (((c4 * 4) & 127) >> 2)] = r;
    }
    if (tid < HH)
        g_b[tid * TT + t] = 1.f / (1.f + expf(-beta[(size_t)t * HH + tid]));
}

// ============================================================================
// Phase 1b: group operators + solve/output matrices. One warp per group.
// ============================================================================
__global__ void __launch_bounds__(128)
group_prep_kernel()
{
    const int h    = blockIdx.y;
    const int g    = blockIdx.x * 4 + (threadIdx.x >> 5);
    const int lane = threadIdx.x & 31;

    const size_t base = ((size_t)h * TT + (size_t)g * GS) * DD;
    const float4* kp4 = (const float4*)(g_k   + base);
    const float4* dp4 = (const float4*)(g_dec + base);
    const float4* qp4 = (const float4*)(g_q   + base);
    float4* KGout = (float4*)(g_KG + base);
    float4* QGout = (float4*)(g_QG + base);
    float4* KPout = (float4*)(g_KP + base);
    float4* G7out = (float4*)(g_G7 + ((size_t)h * NG + g) * DD);

    float4 dv[GS], kv[GS], qv[GS];
    #pragma unroll
    for (int i = 0; i < GS; i++) {
        dv[i] = dp4[i * 32 + lane];
        kv[i] = kp4[i * 32 + lane];
        qv[i] = qp4[i * 32 + lane];
    }

    // prefix decay products -> KG, QG, G7
    {
        float4 G = make_float4(1.f, 1.f, 1.f, 1.f);
        #pragma unroll
        for (int i = 0; i < GS; i++) {
            G.x *= dv[i].x; G.y *= dv[i].y; G.z *= dv[i].z; G.w *= dv[i].w;
            float4 o;
            o.x = G.x * kv[i].x; o.y = G.y * kv[i].y;
            o.z = G.z * kv[i].z; o.w = G.w * kv[i].w;
            KGout[i * 32 + lane] = o;
            o.x = G.x * qv[i].x; o.y = G.y * qv[i].y;
            o.z = G.z * qv[i].z; o.w = G.w * qv[i].w;
            QGout[i * 32 + lane] = o;
        }
        G7out[lane] = G;
    }

    float r[64];
    #pragma unroll
    for (int i = 0; i < GS; i++) r[i * 9] = dot4(qv[i], kv[i]);

    #pragma unroll
    for (int j = 0; j < GS; j++) {
        float4 w = kv[j];
        #pragma unroll
        for (int i = j + 1; i < GS; i++) {
            w.x *= dv[i].x; w.y *= dv[i].y; w.z *= dv[i].z; w.w *= dv[i].w;
            r[i * 8 + j] = dot4(kv[i], w);   // c_ij (lower)
            r[j * 8 + i] = dot4(qv[i], w);   // cq_ij (upper slot)
        }
        KPout[j * 32 + lane] = w;            // suffix-decayed key
    }

    #pragma unroll
    for (int off = 16; off > 0; off >>= 1) {
        #pragma unroll
        for (int m = 0; m < 64; m++)
            r[m] += __shfl_xor_sync(0xffffffffu, r[m], off);
    }
    if (lane == 0) {
        float* co = g_c + ((size_t)h * NG + g) * 128;
        #pragma unroll
        for (int m = 0; m < 64; m++) co[m] = r[m];
        #pragma unroll
        for (int i = 0; i < GS; i++)
            #pragma unroll
            for (int j = 0; j < GS; j++)
                co[64 + i * 8 + j] = (j < i) ? r[j * 8 + i]
                                  : (j == i) ? r[i * 9] : 0.f;
    }
}

// ============================================================================
// Phase 2: 8-step-group scan, 256 threads, 8 INDEPENDENT warps x 2 columns.
// Lane owns D[4L,4L+4); warp w owns cols {2w, 2w+1} of the 16-col block.
// col = (lane>>4)&1 selects the lane's solve column; myi = (lane>>1)&7 its
// output step (dup pair on lane bit0). No cross-warp communication.
// ============================================================================

#define RSTAGE_SPLIT(r, n, o) do {                                          \
    const bool _hi = (lane & (o)) != 0;                                     \
    _Pragma("unroll")                                                       \
    for (int _j = 0; _j < (n); _j++) {                                      \
        float _send = _hi ? r[_j] : r[_j + (n)];                            \
        float _recv = __shfl_xor_sync(0xffffffffu, _send, (o));             \
        r[_j] = (_hi ? r[_j + (n)] : r[_j]) + _recv;                        \
    }                                                                       \
} while (0)

#define PREFETCH(slot, t0) do {                                             \
    {                                                                       \
        size_t _go = (size_t)((t0) + (tid >> 5)) * DD + (tid & 31) * 4;     \
        cpa16(&sKG[slot][tid >> 5][tid & 31], KGg + _go);                   \
        cpa16(&sQG[slot][tid >> 5][tid & 31], QGg + _go);                   \
        cpa16(&sKP[slot][tid >> 5][tid & 31], KPg + _go);                   \
    }                                                                       \
    if (tid < 32) {                                                         \
        cpa16(&sG7[slot][tid], G7g + (size_t)((t0) >> 3) * DD + tid * 4);   \
    } else if (tid < 64) {                                                  \
        int _c = tid - 32;                                                  \
        cpa16(&sv[slot][_c >> 2][(_c & 3) * 4],                             \
              vg + (size_t)((t0) + (_c >> 2)) * DD + (_c & 3) * 4);         \
    } else if (tid < 96) {                                                  \
        int _m = tid - 64;                                                  \
        cpa16(&sc[slot][_m * 4],                                            \
              cg + (size_t)((t0) >> 3) * 128 + _m * 4);                     \
    } else if (tid < 98) {                                                  \
        int _j2 = tid - 96;                                                 \
        cpa16(&sb[slot][_j2 * 4], bg + (t0) + _j2 * 4);                     \
    }                                                                       \
} while (0)

__global__ void __launch_bounds__(256, 1)
kda_scan_kernel(float* __restrict__ out)
{
    __shared__ __align__(16) ulonglong2 sKG[NBUF][GS][32];
    __shared__ __align__(16) ulonglong2 sQG[NBUF][GS][32];
    __shared__ __align__(16) ulonglong2 sKP[NBUF][GS][32];
    __shared__ __align__(16) ulonglong2 sG7[NBUF][32];
    __shared__ __align__(16) float      sv[NBUF][GS][16];
    __shared__ __align__(16) float      sb[NBUF][GS];
    __shared__ __align__(16) float      sc[NBUF][128];

    const int h    = blockIdx.y;
    const int cb   = blockIdx.x;
    const int tid  = threadIdx.x;
    const int lane = tid & 31;
    const int w    = tid >> 5;           // warp: columns {2w, 2w+1}
    const int col  = (lane >> 4) & 1;    // lane's solve/output column (local)
    const int myi  = (lane >> 1) & 7;    // lane's output step
    const int colloc = 2 * w + col;      // column within 16-col block

    const size_t hbase = (size_t)h * TT * DD;
    const float* KGg = g_KG + hbase;
    const float* QGg = g_QG + hbase;
    const float* KPg = g_KP + hbase;
    const float* G7g = g_G7 + (size_t)h * NG * DD;
    const float* vg  = g_v  + hbase + cb * CPB;
    const float* bg  = g_b  + (size_t)h * TT;
    const float* cg  = g_c  + (size_t)h * NG * 128;
    float* op = out + (size_t)h * DD + cb * CPB + colloc;

    // state: st[c][p] = S[D-slice pair p of lane][col 2w+c]
    u64 st[2][2];
    st[0][0] = 0ull; st[0][1] = 0ull; st[1][0] = 0ull; st[1][1] = 0ull;

    PREFETCH(0, 0);
    asm volatile("cp.async.commit_group;" ::: "memory");
    PREFETCH(1, GS);
    asm volatile("cp.async.commit_group;" ::: "memory");

    #pragma unroll 1
    for (int t0 = 0; t0 < TT; t0 += GS) {
        const int slot = (t0 >> 3) % NBUF;
        asm volatile("cp.async.wait_group 1;" ::: "memory");
        __syncthreads();                               // operands ready

        // prefetch 2 groups ahead (into the slot the previous group used)
        if (t0 + 2 * GS < TT) {
            PREFETCH((slot + 2) % NBUF, t0 + 2 * GS);
        }
        asm volatile("cp.async.commit_group;" ::: "memory");

        // ---- dots: r[8c+i] = km partial, x[8c+i] = o partial ----
        float r[16], x[16];
        #pragma unroll
        for (int i = 0; i < GS; i++) {
            ulonglong2 kg = sKG[slot][i][lane];
            #pragma unroll
            for (int c = 0; c < 2; c++) {
                u64 t = mul2(kg.x, st[c][0]);
                t = fma2(kg.y, st[c][1], t);
                r[8 * c + i] = hsum2(t);
            }
            ulonglong2 qg = sQG[slot][i][lane];
            #pragma unroll
            for (int c = 0; c < 2; c++) {
                u64 t = mul2(qg.x, st[c][0]);
                t = fma2(qg.y, st[c][1], t);
                x[8 * c + i] = hsum2(t);
            }
        }

        // ---- reduce: col split at o=16 (both), then km allreduce + x split ----
        RSTAGE_SPLIT(r, 8, 16);
        RSTAGE_SPLIT(x, 8, 16);
        #pragma unroll
        for (int o = 8; o >= 1; o >>= 1) {
            #pragma unroll
            for (int j = 0; j < 8; j++)
                r[j] += __shfl_xor_sync(0xffffffffu, r[j], o);
        }
        RSTAGE_SPLIT(x, 4, 8);
        RSTAGE_SPLIT(x, 2, 4);
        RSTAGE_SPLIT(x, 1, 2);
        x[0] += __shfl_xor_sync(0xffffffffu, x[0], 1);
        // now r[i] = km[i] for col; x[0] = o_partial(myi, col)

        // ---- triangular solve for column col (redundant x16 lanes) ----
        float del[8];
        del[0] = sb[slot][0] * (sv[slot][0][colloc] - r[0]);
        #pragma unroll
        for (int i = 1; i < GS; i++) {
            float acc = r[i];
            #pragma unroll
            for (int j = 0; j < i; j++)
                acc = fmaf(sc[slot][i * 8 + j], del[j], acc);
            del[i] = sb[slot][i] * (sv[slot][i][colloc] - acc);
        }

        // ---- output: o(myi,col) = x[0] + sum_j CQ[myi][j]*del[j] ----
        {
            const float* cqp = &sc[slot][64 + myi * 8];
            float oo = x[0];
            #pragma unroll
            for (int j = 0; j < GS; j++)
                oo = fmaf(cqp[j], del[j], oo);
            if (!(lane & 1)) op[(size_t)(t0 + myi) * HD] = oo;
        }

        // ---- exchange del across the two col-groups (xor 16) ----
        float d0a[8], d1a[8];
        #pragma unroll
        for (int i = 0; i < GS; i++) {
            float other = __shfl_xor_sync(0xffffffffu, del[i], 16);
            d0a[i] = col ? other  : del[i];   // del for local col 0
            d1a[i] = col ? del[i] : other;    // del for local col 1
        }

        // ---- state update st = G7∘st + sum_i KP_i * del_i ----
        {
            ulonglong2 g7 = sG7[slot][lane];
            st[0][0] = mul2(g7.x, st[0][0]); st[0][1] = mul2(g7.y, st[0][1]);
            st[1][0] = mul2(g7.x, st[1][0]); st[1][1] = mul2(g7.y, st[1][1]);
        }
        #pragma unroll
        for (int i = 0; i < GS; i++) {
            ulonglong2 kp = sKP[slot][i][lane];
            u64 p0 = pack2(d0a[i]), p1 = pack2(d1a[i]);
            st[0][0] = fma2(kp.x, p0, st[0][0]); st[0][1] = fma2(kp.y, p0, st[0][1]);
            st[1][0] = fma2(kp.x, p1, st[1][0]); st[1][1] = fma2(kp.y, p1, st[1][1]);
        }
    }
}

// ============================================================================
extern "C" void kernel_launch(void* const* d_in, const int* in_sizes, int n_in,
                              void* d_out, int out_size)
{
    const float* mixed = (const float*)d_in[0];   // [T, 3HD]
    const float* fg    = (const float*)d_in[1];   // [T, HD]
    const float* beta  = (const float*)d_in[2];   // [T, H]
    const float* cw    = (const float*)d_in[3];   // [3HD, 4]
    const float* dtb   = (const float*)d_in[4];   // [H, D]
    const float* alog  = (const float*)d_in[5];   // [H]
    float* out = (float*)d_out;                   // [T, H, D] f32

    dummy_kernel<<<1, 32>>>();                    // keeps ncu slot on the scan
    prep_kernel<<<TT, 256>>>(mixed, fg, beta, cw, dtb, alog);
    group_prep_kernel<<<dim3(NG / 4, HH), 128>>>();
    kda_scan_kernel<<<dim3(NCB, HH), 256>>>(out);
}

// round 15
// speedup vs baseline: 1.0993x; 1.0826x over previous
#include <cuda_runtime.h>
#include <cstdint>

#define TT 8192
#define HH 16
#define DD 128
#define HD (HH * DD)        // 2048
#define C3 (3 * HD)         // 6144
#define NCB 8               // column blocks per head
#define CPB 16              // columns per block
#define GS 8                // steps per smem stage = group size
#define NG (TT / GS)        // 1024 groups per head
#define NBUF 3              // operand stages

typedef unsigned long long u64;

// ---------------- scratch (static device memory; no allocs allowed) --------
__device__ float g_q  [HH * TT * DD];   // [H][T][D]
__device__ float g_k  [HH * TT * DD];   // [H][T][D]
__device__ float g_dec[HH * TT * DD];   // [H][T][D]
__device__ float g_v  [HH * TT * DD];   // [H][T][D]
__device__ float g_KG [HH * TT * DD];   // [H][T][D] G_i∘k_i
__device__ float g_QG [HH * TT * DD];   // [H][T][D] G_i∘q_i
__device__ float g_KP [HH * TT * DD];   // [H][T][D] suffix-decayed keys
__device__ float g_G7 [HH * NG * DD];   // [H][NG][D] full-group decay
__device__ float g_b  [HH * TT];        // [H][T]
__device__ float g_c  [HH * NG * 128];  // [H][NG][128]: [0..64) solve C, [64..128) CQ

// ---------------- packed f32x2 helpers (sm_103a) ---------------------------
__device__ __forceinline__ u64 fma2(u64 a, u64 b, u64 c) {
    u64 d; asm("fma.rn.f32x2 %0, %1, %2, %3;" : "=l"(d) : "l"(a), "l"(b), "l"(c)); return d;
}
__device__ __forceinline__ u64 mul2(u64 a, u64 b) {
    u64 d; asm("mul.rn.f32x2 %0, %1, %2;" : "=l"(d) : "l"(a), "l"(b)); return d;
}
__device__ __forceinline__ float hsum2(u64 a) {
    float x, y; asm("mov.b64 {%0, %1}, %2;" : "=f"(x), "=f"(y) : "l"(a)); return x + y;
}
__device__ __forceinline__ u64 pack2(float x) {
    u64 d; asm("mov.b64 %0, {%1, %1};" : "=l"(d) : "f"(x)); return d;
}
__device__ __forceinline__ void cpa16(void* dst, const void* src) {
    unsigned d = (unsigned)__cvta_generic_to_shared(dst);
    asm volatile("cp.async.ca.shared.global [%0], [%1], 16;" :: "r"(d), "l"(src));
}
__device__ __forceinline__ float softplusf(float x) {
    return (x > 20.f) ? x : log1pf(expf(x));
}
__device__ __forceinline__ float dot4(float4 a, float4 b) {
    return a.x * b.x + a.y * b.y + a.z * b.z + a.w * b.w;
}

// ---------------- dummy kernel: keeps ncu's profiled slot on the scan ------
__global__ void dummy_kernel() {}

// ============================================================================
// Phase 1: conv1d + SiLU, l2norm(q,k), gates  -> transposed [H][T][D] scratch
// ============================================================================
__global__ void prep_kernel(const float* __restrict__ xin,   // [T, 3HD]
                            const float* __restrict__ fg,    // [T, HD]
                            const float* __restrict__ beta,  // [T, H]
                            const float* __restrict__ cw,    // [3HD, 4]
                            const float* __restrict__ dtb,   // [H, D]
                            const float* __restrict__ alog)  // [H]
{
    const int t   = blockIdx.x;
    const int tid = threadIdx.x;                 // 256 threads

    __shared__ float sbuf[C3];
    __shared__ float snorm[32];
    __shared__ float snegA[HH];

    if (tid < HH) snegA[tid] = -expf(alog[tid]);

    const float4* x4  = (const float4*)xin;      // [T, 1536]
    const float4* w4  = (const float4*)cw;
    float4* sbuf4 = (float4*)sbuf;

    #pragma unroll
    for (int it = 0; it < 6; it++) {
        int c4 = tid + it * 256;                 // 0..1535
        float4 w0 = w4[c4 * 4 + 0];
        float4 w1 = w4[c4 * 4 + 1];
        float4 w2 = w4[c4 * 4 + 2];
        float4 w3 = w4[c4 * 4 + 3];
        float4 a0 = x4[(size_t)t * 1536 + c4];
        float4 acc;
        acc.x = a0.x * w0.w; acc.y = a0.y * w1.w;
        acc.z = a0.z * w2.w; acc.w = a0.w * w3.w;
        if (t >= 1) {
            float4 a = x4[(size_t)(t - 1) * 1536 + c4];
            acc.x += a.x * w0.z; acc.y += a.y * w1.z;
            acc.z += a.z * w2.z; acc.w += a.w * w3.z;
        }
        if (t >= 2) {
            float4 a = x4[(size_t)(t - 2) * 1536 + c4];
            acc.x += a.x * w0.y; acc.y += a.y * w1.y;
            acc.z += a.z * w2.y; acc.w += a.w * w3.y;
        }
        if (t >= 3) {
            float4 a = x4[(size_t)(t - 3) * 1536 + c4];
            acc.x += a.x * w0.x; acc.y += a.y * w1.x;
            acc.z += a.z * w2.x; acc.w += a.w * w3.x;
        }
        acc.x = acc.x / (1.f + expf(-acc.x));
        acc.y = acc.y / (1.f + expf(-acc.y));
        acc.z = acc.z / (1.f + expf(-acc.z));
        acc.w = acc.w / (1.f + expf(-acc.w));
        sbuf4[c4] = acc;
    }
    __syncthreads();

    const int wid = tid >> 5, lane = tid & 31;
    for (int g = wid; g < 32; g += 8) {
        const int base = g * 128;
        float v0 = sbuf[base + lane];
        float v1 = sbuf[base + 32 + lane];
        float v2 = sbuf[base + 64 + lane];
        float v3 = sbuf[base + 96 + lane];
        float ss = v0 * v0 + v1 * v1 + v2 * v2 + v3 * v3;
        #pragma unroll
        for (int off = 16; off > 0; off >>= 1)
            ss += __shfl_xor_sync(0xffffffffu, ss, off);
        if (lane == 0) snorm[g] = rsqrtf(ss + 1e-6f);
    }
    __syncthreads();

    const float qscale = 0.08838834764831845f;   // D^-0.5
    #pragma unroll
    for (int it = 0; it < 6; it++) {
        int c4 = tid + it * 256;
        int c  = c4 * 4;
        float4 val = sbuf4[c4];
        if (c < HD) {
            int h = c >> 7, d = c & 127;
            float sc = snorm[h] * qscale;
            val.x *= sc; val.y *= sc; val.z *= sc; val.w *= sc;
            ((float4*)g_q)[((size_t)h * TT + t) * 32 + (d >> 2)] = val;
        } else if (c < 2 * HD) {
            int cc = c - HD; int h = cc >> 7, d = cc & 127;
            float sc = snorm[16 + h];
            val.x *= sc; val.y *= sc; val.z *= sc; val.w *= sc;
            ((float4*)g_k)[((size_t)h * TT + t) * 32 + (d >> 2)] = val;
        } else {
            int cc = c - 2 * HD; int h = cc >> 7, d = cc & 127;
            ((float4*)g_v)[((size_t)h * TT + t) * 32 + (d >> 2)] = val;
        }
    }

    const float4* fg4  = (const float4*)fg;
    const float4* dtb4 = (const float4*)dtb;
    #pragma unroll
    for (int it = 0; it < 2; it++) {
        int c4 = tid + it * 256;                 // 0..511
        int h  = (c4 * 4) >> 7;
        float na = snegA[h];
        float4 gg = fg4[(size_t)t * 512 + c4];
        float4 bb = dtb4[c4];
        float4 r;
        r.x = expf(na * softplusf(gg.x + bb.x));
        r.y = expf(na * softplusf(gg.y + bb.y));
        r.z = expf(na * softplusf(gg.z + bb.z));
        r.w = expf(na * softplusf(gg.w + bb.w));
        ((float4*)g_dec)[((size_t)h * TT + t) * 32 + (((c4 * 4) & 127) >> 2)] = r;
    }
    if (tid < HH)
        g_b[tid * TT + t] = 1.f / (1.f + expf(-beta[(size_t)t * HH + tid]));
}

// ============================================================================
// Phase 1b: group operators + solve/output matrices. One warp per group.
// ============================================================================
__global__ void __launch_bounds__(128)
group_prep_kernel()
{
    const int h    = blockIdx.y;
    const int g    = blockIdx.x * 4 + (threadIdx.x >> 5);
    const int lane = threadIdx.x & 31;

    const size_t base = ((size_t)h * TT + (size_t)g * GS) * DD;
    const float4* kp4 = (const float4*)(g_k   + base);
    const float4* dp4 = (const float4*)(g_dec + base);
    const float4* qp4 = (const float4*)(g_q   + base);
    float4* KGout = (float4*)(g_KG + base);
    float4* QGout = (float4*)(g_QG + base);
    float4* KPout = (float4*)(g_KP + base);
    float4* G7out = (float4*)(g_G7 + ((size_t)h * NG + g) * DD);

    float4 dv[GS], kv[GS], qv[GS];
    #pragma unroll
    for (int i = 0; i < GS; i++) {
        dv[i] = dp4[i * 32 + lane];
        kv[i] = kp4[i * 32 + lane];
        qv[i] = qp4[i * 32 + lane];
    }

    // prefix decay products -> KG, QG, G7
    {
        float4 G = make_float4(1.f, 1.f, 1.f, 1.f);
        #pragma unroll
        for (int i = 0; i < GS; i++) {
            G.x *= dv[i].x; G.y *= dv[i].y; G.z *= dv[i].z; G.w *= dv[i].w;
            float4 o;
            o.x = G.x * kv[i].x; o.y = G.y * kv[i].y;
            o.z = G.z * kv[i].z; o.w = G.w * kv[i].w;
            KGout[i * 32 + lane] = o;
            o.x = G.x * qv[i].x; o.y = G.y * qv[i].y;
            o.z = G.z * qv[i].z; o.w = G.w * qv[i].w;
            QGout[i * 32 + lane] = o;
        }
        G7out[lane] = G;
    }

    float r[64];
    #pragma unroll
    for (int i = 0; i < GS; i++) r[i * 9] = dot4(qv[i], kv[i]);

    #pragma unroll
    for (int j = 0; j < GS; j++) {
        float4 w = kv[j];
        #pragma unroll
        for (int i = j + 1; i < GS; i++) {
            w.x *= dv[i].x; w.y *= dv[i].y; w.z *= dv[i].z; w.w *= dv[i].w;
            r[i * 8 + j] = dot4(kv[i], w);   // c_ij (lower)
            r[j * 8 + i] = dot4(qv[i], w);   // cq_ij (upper slot)
        }
        KPout[j * 32 + lane] = w;            // suffix-decayed key
    }

    #pragma unroll
    for (int off = 16; off > 0; off >>= 1) {
        #pragma unroll
        for (int m = 0; m < 64; m++)
            r[m] += __shfl_xor_sync(0xffffffffu, r[m], off);
    }
    if (lane == 0) {
        float* co = g_c + ((size_t)h * NG + g) * 128;
        #pragma unroll
        for (int m = 0; m < 64; m++) co[m] = r[m];
        #pragma unroll
        for (int i = 0; i < GS; i++)
            #pragma unroll
            for (int j = 0; j < GS; j++)
                co[64 + i * 8 + j] = (j < i) ? r[j * 8 + i]
                                  : (j == i) ? r[i * 9] : 0.f;
    }
}

// ============================================================================
// Phase 2: 8-step-group scan (R12 layout: 128 thr, 4 warps x 4 cols; lane
// owns D[4L,4L+4)), with: single barrier/group (NBUF=3), column-parallel
// triangular solve (short chain), smem del broadcast (no shfl permute net).
// ============================================================================

#define RSTAGE_SPLIT(r, n, o) do {                                          \
    const bool _hi = (lane & (o)) != 0;                                     \
    _Pragma("unroll")                                                       \
    for (int _j = 0; _j < (n); _j++) {                                      \
        float _send = _hi ? r[_j] : r[_j + (n)];                            \
        float _recv = __shfl_xor_sync(0xffffffffu, _send, (o));             \
        r[_j] = (_hi ? r[_j + (n)] : r[_j]) + _recv;                        \
    }                                                                       \
} while (0)

#define PREFETCH(slot, t0) do {                                             \
    _Pragma("unroll")                                                       \
    for (int _j = 0; _j < 2; _j++) {                                        \
        int _c = tid + _j * 128;                                            \
        int _st = _c >> 5, _cc = _c & 31;                                   \
        size_t _go = (size_t)((t0) + _st) * DD + _cc * 4;                   \
        cpa16(&sKG[slot][_st][_cc], KGg + _go);                             \
        cpa16(&sQG[slot][_st][_cc], QGg + _go);                             \
        cpa16(&sKP[slot][_st][_cc], KPg + _go);                             \
    }                                                                       \
    if (tid < 32) {                                                         \
        int _st = tid >> 2, _part = tid & 3;                                \
        cpa16(&sv[slot][_st][_part * 4],                                    \
              vg + (size_t)((t0) + (_st)) * DD + _part * 4);                \
    } else if (tid < 34) {                                                  \
        int _j2 = tid - 32;                                                 \
        cpa16(&sb[slot][_j2 * 4], bg + (t0) + _j2 * 4);                     \
    } else if (tid < 66) {                                                  \
        int _m = tid - 34;                                                  \
        cpa16(&sc[slot][_m * 4],                                            \
              cg + (size_t)((t0) >> 3) * 128 + _m * 4);                     \
    } else if (tid < 98) {                                                  \
        int _cc = tid - 66;                                                 \
        cpa16(&sG7[slot][_cc], G7g + (size_t)((t0) >> 3) * DD + _cc * 4);   \
    }                                                                       \
} while (0)

__global__ void __launch_bounds__(128, 1)
kda_scan_kernel(float* __restrict__ out)
{
    __shared__ __align__(16) ulonglong2 sKG[NBUF][GS][32];
    __shared__ __align__(16) ulonglong2 sQG[NBUF][GS][32];
    __shared__ __align__(16) ulonglong2 sKP[NBUF][GS][32];
    __shared__ __align__(16) ulonglong2 sG7[NBUF][32];
    __shared__ __align__(16) float      sv[NBUF][GS][16];
    __shared__ __align__(16) float      sb[NBUF][GS];
    __shared__ __align__(16) float      sc[NBUF][128];
    __shared__ __align__(16) float      sdel[4][GS][4];   // per-warp del rows

    const int h    = blockIdx.y;
    const int cb   = blockIdx.x;
    const int tid  = threadIdx.x;
    const int lane = tid & 31;
    const int w    = tid >> 5;           // warp: columns [4w, 4w+4)
    const int cgrp = (lane >> 3) & 3;    // lane's solve/output column
    const int myi  = lane & 7;           // lane's output step
    const int colloc = 4 * w + cgrp;

    const size_t hbase = (size_t)h * TT * DD;
    const float* KGg = g_KG + hbase;
    const float* QGg = g_QG + hbase;
    const float* KPg = g_KP + hbase;
    const float* G7g = g_G7 + (size_t)h * NG * DD;
    const float* vg  = g_v  + hbase + cb * CPB;
    const float* bg  = g_b  + (size_t)h * TT;
    const float* cg  = g_c  + (size_t)h * NG * 128;
    float* op = out + (size_t)h * DD + cb * CPB + colloc;

    // state: st[c][p] = S[D-slice pair p of lane][col 4w+c]
    u64 st[4][2];
    #pragma unroll
    for (int c = 0; c < 4; c++) { st[c][0] = 0ull; st[c][1] = 0ull; }

    PREFETCH(0, 0);
    asm volatile("cp.async.commit_group;" ::: "memory");
    PREFETCH(1, GS);
    asm volatile("cp.async.commit_group;" ::: "memory");

    #pragma unroll 1
    for (int t0 = 0; t0 < TT; t0 += GS) {
        const int slot = (t0 >> 3) % NBUF;
        asm volatile("cp.async.wait_group 1;" ::: "memory");
        __syncthreads();                               // operands ready

        // prefetch 2 ahead into the slot the previous group used (all warps
        // are past it thanks to this barrier)
        if (t0 + 2 * GS < TT) {
            PREFETCH((slot + 2) % NBUF, t0 + 2 * GS);
        }
        asm volatile("cp.async.commit_group;" ::: "memory");

        // ---- phase A: per-lane partial dots ----
        float r[32], x[32];
        #pragma unroll
        for (int i = 0; i < GS; i++) {
            ulonglong2 kg = sKG[slot][i][lane];
            #pragma unroll
            for (int c = 0; c < 4; c++) {
                u64 t = mul2(kg.x, st[c][0]);
                t = fma2(kg.y, st[c][1], t);
                r[8 * c + i] = hsum2(t);
            }
            ulonglong2 qg = sQG[slot][i][lane];
            #pragma unroll
            for (int c = 0; c < 4; c++) {
                u64 t = mul2(qg.x, st[c][0]);
                t = fma2(qg.y, st[c][1], t);
                x[8 * c + i] = hsum2(t);
            }
        }

        // off-chain scalars for the solve
        float sbv[8], bv[8];
        #pragma unroll
        for (int i = 0; i < GS; i++) {
            sbv[i] = sb[slot][i];
            bv[i]  = sbv[i] * sv[slot][i][colloc];
        }

        // ---- phase B: split stages, km all-reduce, x full split ----
        RSTAGE_SPLIT(r, 16, 16);  RSTAGE_SPLIT(x, 16, 16);
        RSTAGE_SPLIT(r,  8,  8);  RSTAGE_SPLIT(x,  8,  8);
        #pragma unroll
        for (int o = 4; o >= 1; o >>= 1) {
            #pragma unroll
            for (int j = 0; j < 8; j++)
                r[j] += __shfl_xor_sync(0xffffffffu, r[j], o);
        }
        RSTAGE_SPLIT(x, 4, 4);
        RSTAGE_SPLIT(x, 2, 2);
        RSTAGE_SPLIT(x, 1, 1);
        // r[i] = km[i] for col cgrp; x[0] = o_partial(myi, cgrp)

        // ---- phase C: column-parallel triangular solve (short chain) ----
        // del[i] = b_i*(v_i) - b_i*acc_i with acc accumulating c_ij*del_j in
        // ascending j (same per-element add order as row-wise -> same math).
        float del[8];
        del[0] = fmaf(-sbv[0], r[0], bv[0]);
        #pragma unroll
        for (int j = 0; j < GS - 1; j++) {
            #pragma unroll
            for (int i = j + 1; i < GS; i++)
                r[i] = fmaf(sc[slot][i * 8 + j], del[j], r[i]);
            del[j + 1] = fmaf(-sbv[j + 1], r[j + 1], bv[j + 1]);
        }

        // ---- publish del to this warp's smem row (1 wavefront) ----
        #pragma unroll
        for (int i = 0; i < GS; i++)
            if (myi == i) sdel[w][i][cgrp] = del[i];
        __syncwarp();

        // ---- phase D: state update st = G7∘st + sum_i KP_i * del_i ----
        {
            ulonglong2 g7 = sG7[slot][lane];
            #pragma unroll
            for (int c = 0; c < 4; c++) {
                st[c][0] = mul2(g7.x, st[c][0]);
                st[c][1] = mul2(g7.y, st[c][1]);
            }
        }
        #pragma unroll
        for (int i = 0; i < GS; i++) {
            float4 dr = *(const float4*)&sdel[w][i][0];   // broadcast
            ulonglong2 kp = sKP[slot][i][lane];
            u64 d0 = pack2(dr.x), d1 = pack2(dr.y);
            u64 d2 = pack2(dr.z), d3 = pack2(dr.w);
            st[0][0] = fma2(kp.x, d0, st[0][0]); st[0][1] = fma2(kp.y, d0, st[0][1]);
            st[1][0] = fma2(kp.x, d1, st[1][0]); st[1][1] = fma2(kp.y, d1, st[1][1]);
            st[2][0] = fma2(kp.x, d2, st[2][0]); st[2][1] = fma2(kp.y, d2, st[2][1]);
            st[3][0] = fma2(kp.x, d3, st[3][0]); st[3][1] = fma2(kp.y, d3, st[3][1]);
        }

        // ---- output (off critical path): one STG per lane ----
        {
            const float* cqp = &sc[slot][64 + myi * 8];
            float oo = x[0];
            #pragma unroll
            for (int j = 0; j < GS; j++)
                oo = fmaf(cqp[j], del[j], oo);
            op[(size_t)(t0 + myi) * HD] = oo;
        }
    }
}

// ============================================================================
extern "C" void kernel_launch(void* const* d_in, const int* in_sizes, int n_in,
                              void* d_out, int out_size)
{
    const float* mixed = (const float*)d_in[0];   // [T, 3HD]
    const float* fg    = (const float*)d_in[1];   // [T, HD]
    const float* beta  = (const float*)d_in[2];   // [T, H]
    const float* cw    = (const float*)d_in[3];   // [3HD, 4]
    const float* dtb   = (const float*)d_in[4];   // [H, D]
    const float* alog  = (const float*)d_in[5];   // [H]
    float* out = (float*)d_out;                   // [T, H, D] f32

    dummy_kernel<<<1, 32>>>();                    // keeps ncu slot on the scan
    prep_kernel<<<TT, 256>>>(mixed, fg, beta, cw, dtb, alog);
    group_prep_kernel<<<dim3(NG / 4, HH), 128>>>();
    kda_scan_kernel<<<dim3(NCB, HH), 128>>>(out);
}